// round 4
// baseline (speedup 1.0000x reference)
#include <cuda_runtime.h>
#include <math.h>

// ---------------------------------------------------------------------------
// Problem constants
// ---------------------------------------------------------------------------
#define BATCH 32
#define SEQ   512
#define DMODEL 512
#define DTIME  256
#define NHEAD  8
#define HD     64
#define VD     32
#define DFF    2048
#define NROWS  (BATCH * SEQ)      // 16384
#define DCAT   (DMODEL + DTIME)   // 768
#define MTN    16

// ---------------------------------------------------------------------------
// Scratch (device globals; no runtime allocation)
// ---------------------------------------------------------------------------
__device__ float g_tmp [ (size_t)NROWS * DMODEL ];
__device__ float g_xtok[ (size_t)NROWS * DMODEL ];
__device__ float g_xtim[ (size_t)NROWS * DTIME  ];
__device__ float g_qkv [ (size_t)NROWS * 3 * DMODEL ];
__device__ float g_attn[ (size_t)NROWS * DMODEL ];
__device__ float g_diag[ (size_t)NROWS * NHEAD  ];
__device__ float g_xc  [ (size_t)NROWS * DCAT   ];
__device__ float g_ff1 [ (size_t)NROWS * DFF    ];
__device__ float g_ff2 [ (size_t)NROWS * DCAT   ];
__device__ float g_pool[ (size_t)BATCH * (SEQ/MTN) * DCAT ];
__device__ float g_fin [ (size_t)BATCH * (SEQ/MTN) * DTIME ];

// ---------------------------------------------------------------------------
// Helpers
// ---------------------------------------------------------------------------
__device__ __forceinline__ float f2tf(float x) {
    unsigned r;
    asm("cvt.rna.tf32.f32 %0, %1;" : "=r"(r) : "f"(x));
    return __uint_as_float(r);
}

__device__ __forceinline__ int perm8(int j) {   // k-pair permutation within 8
    return (j < 4) ? 2 * j : 2 * (j - 4) + 1;
}

__device__ __forceinline__ void mma_tf32(float* d, const float* a, const float* b) {
    asm volatile(
        "mma.sync.aligned.m16n8k8.row.col.f32.tf32.tf32.f32 "
        "{%0,%1,%2,%3},{%4,%5,%6,%7},{%8,%9},{%0,%1,%2,%3};\n"
        : "+f"(d[0]), "+f"(d[1]), "+f"(d[2]), "+f"(d[3])
        : "r"(__float_as_uint(a[0])), "r"(__float_as_uint(a[1])),
          "r"(__float_as_uint(a[2])), "r"(__float_as_uint(a[3])),
          "r"(__float_as_uint(b[0])), "r"(__float_as_uint(b[1])));
}

// ---------------------------------------------------------------------------
// Warp-per-row LayerNorm (optionally *(1+diag_head), optionally +res)
// ---------------------------------------------------------------------------
__global__ __launch_bounds__(256) void ln_warp(
    const float* __restrict__ in, int istride,
    const float* __restrict__ res, int rstride,
    const float* __restrict__ diag,
    const float* __restrict__ g, const float* __restrict__ b,
    float* __restrict__ out, int ostride, int D)
{
    const int lane = threadIdx.x & 31;
    const int row  = blockIdx.x * 8 + (threadIdx.x >> 5);
    const float* ip = in + (size_t)row * istride;
    const int nv = D >> 7;

    float v[16];
    float sum = 0.f;
#pragma unroll
    for (int w = 0; w < 4; ++w) {
        if (w < nv) {
            int c = w * 128 + lane * 4;
            float4 t = *(const float4*)(ip + c);
            if (diag) {
                float dm = 1.f + diag[(size_t)row * NHEAD + (c >> 5)];
                t.x *= dm; t.y *= dm; t.z *= dm; t.w *= dm;
            }
            if (res) {
                const float* rp = res + (size_t)row * rstride + c;
                t.x += rp[0]; t.y += rp[1]; t.z += rp[2]; t.w += rp[3];
            }
            v[w*4+0] = t.x; v[w*4+1] = t.y; v[w*4+2] = t.z; v[w*4+3] = t.w;
            sum += t.x + t.y + t.z + t.w;
        }
    }
#pragma unroll
    for (int o = 16; o; o >>= 1) sum += __shfl_xor_sync(0xffffffffu, sum, o);
    const float mean = sum / D;

    float vs = 0.f;
#pragma unroll
    for (int w = 0; w < 4; ++w)
        if (w < nv)
#pragma unroll
            for (int q = 0; q < 4; ++q) {
                float d2 = v[w*4+q] - mean;
                vs += d2 * d2;
            }
#pragma unroll
    for (int o = 16; o; o >>= 1) vs += __shfl_xor_sync(0xffffffffu, vs, o);
    const float rstd = rsqrtf(vs / D + 1e-5f);

#pragma unroll
    for (int w = 0; w < 4; ++w) {
        if (w < nv) {
            int c = w * 128 + lane * 4;
            float4 o4;
            o4.x = (v[w*4+0] - mean) * rstd * g[c+0] + b[c+0];
            o4.y = (v[w*4+1] - mean) * rstd * g[c+1] + b[c+1];
            o4.z = (v[w*4+2] - mean) * rstd * g[c+2] + b[c+2];
            o4.w = (v[w*4+3] - mean) * rstd * g[c+3] + b[c+3];
            *(float4*)(out + (size_t)row * ostride + c) = o4;
        }
    }
}

// ---------------------------------------------------------------------------
// tf32 tensor-core NT GEMM (known-good)
// ---------------------------------------------------------------------------
__global__ __launch_bounds__(256) void gemm_tf32(
    const float* __restrict__ A, const float* __restrict__ W,
    const float* __restrict__ bias, float* __restrict__ C,
    int N, int M, int K, int act)
{
    __shared__ float As[2][128][24];
    __shared__ float Bs[2][128][24];

    const int tid  = threadIdx.x;
    const int lane = tid & 31;
    const int warp = tid >> 5;
    const int wm = (warp & 1) * 64;
    const int wn = (warp >> 1) * 32;
    const int r4 = lane >> 2;
    const int c2 = (lane & 3) * 2;

    const int row0 = blockIdx.y * 128;
    const int col0 = blockIdx.x * 128;

    const int lrow = tid >> 1;
    const int lk   = (tid & 1) * 8;

    const float* Ap = A + (size_t)(row0 + lrow) * K + lk;
    const float* Wp = W + (size_t)(col0 + lrow) * K + lk;

    float acc[4][4][4];
#pragma unroll
    for (int i = 0; i < 4; ++i)
#pragma unroll
        for (int j = 0; j < 4; ++j)
#pragma unroll
            for (int q = 0; q < 4; ++q) acc[i][j][q] = 0.f;

    float4 ra0, ra1, rb0, rb1;

#define LOAD_TILE(kt)                                            \
    do {                                                         \
        const int k0_ = (kt) * 16;                               \
        ra0 = *(const float4*)(Ap + k0_);                        \
        ra1 = *(const float4*)(Ap + k0_ + 4);                    \
        rb0 = *(const float4*)(Wp + k0_);                        \
        rb1 = *(const float4*)(Wp + k0_ + 4);                    \
    } while (0)

#define STORE_TILE(bb)                                                        \
    do {                                                                      \
        float* da = &As[bb][lrow][lk];                                        \
        float* db = &Bs[bb][lrow][lk];                                        \
        ((float2*)da)[0] = make_float2(f2tf(ra0.x), f2tf(ra1.x));             \
        ((float2*)da)[1] = make_float2(f2tf(ra0.y), f2tf(ra1.y));             \
        ((float2*)da)[2] = make_float2(f2tf(ra0.z), f2tf(ra1.z));             \
        ((float2*)da)[3] = make_float2(f2tf(ra0.w), f2tf(ra1.w));             \
        ((float2*)db)[0] = make_float2(f2tf(rb0.x), f2tf(rb1.x));             \
        ((float2*)db)[1] = make_float2(f2tf(rb0.y), f2tf(rb1.y));             \
        ((float2*)db)[2] = make_float2(f2tf(rb0.z), f2tf(rb1.z));             \
        ((float2*)db)[3] = make_float2(f2tf(rb0.w), f2tf(rb1.w));             \
    } while (0)

    const int NT = K >> 4;
    LOAD_TILE(0);
    STORE_TILE(0);
    __syncthreads();

    for (int kt = 0; kt < NT; ++kt) {
        const int buf = kt & 1;
        if (kt + 1 < NT) LOAD_TILE(kt + 1);

#pragma unroll
        for (int s = 0; s < 2; ++s) {
            const int ko = s * 8;
            float a[4][4], b[4][2];
#pragma unroll
            for (int mt = 0; mt < 4; ++mt) {
                float2 t0 = *(const float2*)&As[buf][wm + mt * 16 + r4][ko + c2];
                float2 t1 = *(const float2*)&As[buf][wm + mt * 16 + 8 + r4][ko + c2];
                a[mt][0] = t0.x; a[mt][1] = t1.x; a[mt][2] = t0.y; a[mt][3] = t1.y;
            }
#pragma unroll
            for (int nt = 0; nt < 4; ++nt) {
                float2 tb = *(const float2*)&Bs[buf][wn + nt * 8 + r4][ko + c2];
                b[nt][0] = tb.x; b[nt][1] = tb.y;
            }
#pragma unroll
            for (int mt = 0; mt < 4; ++mt)
#pragma unroll
                for (int nt = 0; nt < 4; ++nt)
                    mma_tf32(acc[mt][nt], a[mt], b[nt]);
        }

        if (kt + 1 < NT) {
            STORE_TILE(buf ^ 1);
            __syncthreads();
        }
    }
#undef LOAD_TILE
#undef STORE_TILE

#pragma unroll
    for (int mt = 0; mt < 4; ++mt) {
        const int row = row0 + wm + mt * 16 + r4;
#pragma unroll
        for (int nt = 0; nt < 4; ++nt) {
            const int col = col0 + wn + nt * 8 + c2;
            const float b0 = bias[col], b1 = bias[col + 1];
            float v[4];
            v[0] = acc[mt][nt][0] + b0;
            v[1] = acc[mt][nt][1] + b1;
            v[2] = acc[mt][nt][2] + b0;
            v[3] = acc[mt][nt][3] + b1;
            if (act == 1) {
#pragma unroll
                for (int q = 0; q < 4; ++q) v[q] = fmaxf(v[q], 0.f);
            } else if (act == 2) {
#pragma unroll
                for (int q = 0; q < 4; ++q)
                    v[q] = 0.5f * v[q] * (1.f + erff(v[q] * 0.70710678118654752f));
            }
            *(float2*)&C[(size_t)row * M + col]       = make_float2(v[0], v[1]);
            *(float2*)&C[(size_t)(row + 8) * M + col] = make_float2(v[2], v[3]);
        }
    }
}

// ---------------------------------------------------------------------------
// Tensor-core flash attention, 128-row Q tile, 256 threads (8 warps x 16 rows).
// split-tf32 QK^T, tf32 PV, __expf softmax, diag extraction.
// grid (SEQ/128, NHEAD, BATCH). Dynamic smem 144 KB:
//   Qh[128x72], Ql[128x72], Kh[64x72], Kl[64x72], Ps[128x72]
// V^T reuses Kh after S is computed.
// ---------------------------------------------------------------------------
#define ATT_STRIDE 72
#define ATT_QBUF (128 * ATT_STRIDE)
#define ATT_KBUF (64 * ATT_STRIDE)
#define ATT_SMEM ((3 * ATT_QBUF + 2 * ATT_KBUF) * (int)sizeof(float))  // 147456

__global__ __launch_bounds__(256) void attn_tc(
    const float* __restrict__ qkv,
    float* __restrict__ attn_out,
    float* __restrict__ diag_out)
{
    extern __shared__ float sm[];
    float* Qh = sm;
    float* Ql = Qh + ATT_QBUF;
    float* Kh = Ql + ATT_QBUF;
    float* Kl = Kh + ATT_KBUF;
    float* Ps = Kl + ATT_KBUF;

    const int qt = blockIdx.x, h = blockIdx.y, b = blockIdx.z;
    const int tid  = threadIdx.x;
    const int lane = tid & 31, warp = tid >> 5;
    const int r4 = lane >> 2;
    const int c2 = (lane & 3) * 2;
    const int wr = warp * 16;             // warp q-row base (0..112)
    const size_t rowbase = (size_t)b * SEQ;
    const int q0 = qt * 128;
    const int qoff = h * HD;

    // ---- load Q (scaled, split hi/lo, d-pair-permuted) ----
    for (int i = tid; i < 2048; i += 256) {
        int r = i >> 4, c4 = (i & 15) << 2;
        float4 v = *(const float4*)(qkv + (rowbase + q0 + r) * 1536 + qoff + c4);
        float vv[4] = {v.x, v.y, v.z, v.w};
#pragma unroll
        for (int j = 0; j < 4; ++j) {
            int d = c4 + j;
            int col = (d & ~7) + perm8(d & 7);
            float x  = vv[j] * 0.125f;
            float hi = f2tf(x);
            Qh[r * ATT_STRIDE + col] = hi;
            Ql[r * ATT_STRIDE + col] = f2tf(x - hi);
        }
    }

    float oacc[8][4];
#pragma unroll
    for (int nf = 0; nf < 8; ++nf)
#pragma unroll
        for (int q = 0; q < 4; ++q) oacc[nf][q] = 0.f;

    float mA = -1e30f, mB = -1e30f, lA = 0.f, lB = 0.f, duA = 0.f, duB = 0.f;

    const int p0 = perm8(c2);
    const int p1 = perm8(c2 + 1);

    for (int kt = 0; kt < 8; ++kt) {
        const int kb = kt * 64;
        __syncthreads();               // prev PV reads of Kh done / Q load (iter 0)

        // ---- load K tile (split hi/lo) ----
        for (int i = tid; i < 1024; i += 256) {
            int r = i >> 4, c4 = (i & 15) << 2;
            float4 v = *(const float4*)(qkv + (rowbase + kb + r) * 1536 + 512 + qoff + c4);
            float vv[4] = {v.x, v.y, v.z, v.w};
#pragma unroll
            for (int j = 0; j < 4; ++j) {
                int d = c4 + j;
                int col = (d & ~7) + perm8(d & 7);
                float hi = f2tf(vv[j]);
                Kh[r * ATT_STRIDE + col] = hi;
                Kl[r * ATT_STRIDE + col] = f2tf(vv[j] - hi);
            }
        }
        __syncthreads();

        // ---- S = Q K^T  (3-term split tf32) ----
        float sacc[8][4];
#pragma unroll
        for (int nf = 0; nf < 8; ++nf)
#pragma unroll
            for (int q = 0; q < 4; ++q) sacc[nf][q] = 0.f;

#pragma unroll
        for (int kg = 0; kg < 8; ++kg) {
            const int ko = kg * 8 + c2;
            float2 qh0 = *(const float2*)&Qh[(wr + r4) * ATT_STRIDE + ko];
            float2 qh1 = *(const float2*)&Qh[(wr + 8 + r4) * ATT_STRIDE + ko];
            float2 ql0 = *(const float2*)&Ql[(wr + r4) * ATT_STRIDE + ko];
            float2 ql1 = *(const float2*)&Ql[(wr + 8 + r4) * ATT_STRIDE + ko];
            float ah[4] = {qh0.x, qh1.x, qh0.y, qh1.y};
            float al[4] = {ql0.x, ql1.x, ql0.y, ql1.y};
#pragma unroll
            for (int nf = 0; nf < 8; ++nf) {
                float2 bh = *(const float2*)&Kh[(nf * 8 + r4) * ATT_STRIDE + ko];
                float2 bl = *(const float2*)&Kl[(nf * 8 + r4) * ATT_STRIDE + ko];
                float bhv[2] = {bh.x, bh.y};
                float blv[2] = {bl.x, bl.y};
                mma_tf32(sacc[nf], ah, bhv);
                mma_tf32(sacc[nf], ah, blv);
                mma_tf32(sacc[nf], al, bhv);
            }
        }

        // ---- online softmax (rows rA = wr+r4, rB = rA+8) ----
        float mxA = -1e30f, mxB = -1e30f;
#pragma unroll
        for (int nf = 0; nf < 8; ++nf) {
            mxA = fmaxf(mxA, fmaxf(sacc[nf][0], sacc[nf][1]));
            mxB = fmaxf(mxB, fmaxf(sacc[nf][2], sacc[nf][3]));
        }
#pragma unroll
        for (int o = 1; o <= 2; o <<= 1) {
            mxA = fmaxf(mxA, __shfl_xor_sync(0xffffffffu, mxA, o));
            mxB = fmaxf(mxB, __shfl_xor_sync(0xffffffffu, mxB, o));
        }
        const float mnA = fmaxf(mA, mxA), mnB = fmaxf(mB, mxB);
        const float cfA = __expf(mA - mnA), cfB = __expf(mB - mnB);
        float sA = 0.f, sB = 0.f;
#pragma unroll
        for (int nf = 0; nf < 8; ++nf) {
            sacc[nf][0] = __expf(sacc[nf][0] - mnA);
            sacc[nf][1] = __expf(sacc[nf][1] - mnA);
            sacc[nf][2] = __expf(sacc[nf][2] - mnB);
            sacc[nf][3] = __expf(sacc[nf][3] - mnB);
            sA += sacc[nf][0] + sacc[nf][1];
            sB += sacc[nf][2] + sacc[nf][3];
        }
#pragma unroll
        for (int o = 1; o <= 2; o <<= 1) {
            sA += __shfl_xor_sync(0xffffffffu, sA, o);
            sB += __shfl_xor_sync(0xffffffffu, sB, o);
        }
        lA = lA * cfA + sA;
        lB = lB * cfB + sB;
        duA *= cfA; duB *= cfB;
#pragma unroll
        for (int nf = 0; nf < 8; ++nf) {
            oacc[nf][0] *= cfA; oacc[nf][1] *= cfA;
            oacc[nf][2] *= cfB; oacc[nf][3] *= cfB;
        }
        mA = mnA; mB = mnB;

        // ---- diag extraction ----
        {
            const int gqA = q0 + wr + r4;
            const int jA = gqA - kb;
            if (jA >= 0 && jA < 64 && ((jA & 7) >> 1) == (lane & 3))
                duA += sacc[jA >> 3][jA & 1];
            const int jB = gqA + 8 - kb;
            if (jB >= 0 && jB < 64 && ((jB & 7) >> 1) == (lane & 3))
                duB += sacc[jB >> 3][2 + (jB & 1)];
        }

        // ---- store P (tf32, kv-pair-permuted) ----
#pragma unroll
        for (int nf = 0; nf < 8; ++nf) {
            float* prA = &Ps[(wr + r4) * ATT_STRIDE + nf * 8];
            float* prB = &Ps[(wr + 8 + r4) * ATT_STRIDE + nf * 8];
            prA[p0] = f2tf(sacc[nf][0]);
            prA[p1] = f2tf(sacc[nf][1]);
            prB[p0] = f2tf(sacc[nf][2]);
            prB[p1] = f2tf(sacc[nf][3]);
        }
        __syncthreads();               // S/P done; Kh free for V^T

        // ---- load V^T into Kh (kv-pair-permuted columns) ----
        for (int i = tid; i < 1024; i += 256) {
            int r = i & 63, c4 = (i >> 6) << 2;
            float4 v = *(const float4*)(qkv + (rowbase + kb + r) * 1536 + 1024 + qoff + c4);
            int pc = (r & ~7) + perm8(r & 7);
            Kh[(c4 + 0) * ATT_STRIDE + pc] = f2tf(v.x);
            Kh[(c4 + 1) * ATT_STRIDE + pc] = f2tf(v.y);
            Kh[(c4 + 2) * ATT_STRIDE + pc] = f2tf(v.z);
            Kh[(c4 + 3) * ATT_STRIDE + pc] = f2tf(v.w);
        }
        __syncthreads();

        // ---- O += P V ----
#pragma unroll
        for (int kg = 0; kg < 8; ++kg) {
            const int ko = kg * 8 + c2;
            float2 pa0 = *(const float2*)&Ps[(wr + r4) * ATT_STRIDE + ko];
            float2 pa1 = *(const float2*)&Ps[(wr + 8 + r4) * ATT_STRIDE + ko];
            float a[4] = {pa0.x, pa1.x, pa0.y, pa1.y};
#pragma unroll
            for (int nf = 0; nf < 8; ++nf) {
                float2 vb = *(const float2*)&Kh[(nf * 8 + r4) * ATT_STRIDE + ko];
                float bv[2] = {vb.x, vb.y};
                mma_tf32(oacc[nf], a, bv);
            }
        }
    }

    // ---- epilogue ----
    const float ivA = 1.f / lA, ivB = 1.f / lB;
    const size_t rA = rowbase + q0 + wr + r4;
    const size_t rB = rA + 8;
#pragma unroll
    for (int nf = 0; nf < 8; ++nf) {
        const int col = qoff + nf * 8 + c2;
        *(float2*)&attn_out[rA * DMODEL + col] =
            make_float2(oacc[nf][0] * ivA, oacc[nf][1] * ivA);
        *(float2*)&attn_out[rB * DMODEL + col] =
            make_float2(oacc[nf][2] * ivB, oacc[nf][3] * ivB);
    }
    float dA = duA * ivA, dB = duB * ivB;
#pragma unroll
    for (int o = 1; o <= 2; o <<= 1) {
        dA += __shfl_xor_sync(0xffffffffu, dA, o);
        dB += __shfl_xor_sync(0xffffffffu, dB, o);
    }
    if ((lane & 3) == 0) {
        diag_out[rA * NHEAD + h] = dA;
        diag_out[rB * NHEAD + h] = dB;
    }
}

// ---------------------------------------------------------------------------
// MaxPool over seq (k=stride=16) producing concatenated [B,32,768]
// ---------------------------------------------------------------------------
__global__ __launch_bounds__(256) void pool_kernel(
    const float* __restrict__ xtok, const float* __restrict__ xtim,
    float* __restrict__ pool)
{
    const int bidx = blockIdx.x;
    const int b = bidx >> 5, ch = bidx & 31;
    const size_t r0 = (size_t)b * SEQ + ch * MTN;
    for (int c = threadIdx.x; c < DCAT; c += 256) {
        float mx = -1e30f;
        if (c < DMODEL) {
            const float* p = xtok + r0 * DMODEL + c;
#pragma unroll
            for (int t = 0; t < MTN; ++t) mx = fmaxf(mx, p[(size_t)t * DMODEL]);
        } else {
            const float* p = xtim + r0 * DTIME + (c - DMODEL);
#pragma unroll
            for (int t = 0; t < MTN; ++t) mx = fmaxf(mx, p[(size_t)t * DTIME]);
        }
        pool[(size_t)bidx * DCAT + c] = mx;
    }
}

// ---------------------------------------------------------------------------
// Host driver
// ---------------------------------------------------------------------------
extern "C" void kernel_launch(void* const* d_in, const int* in_sizes, int n_in,
                              void* d_out, int out_size)
{
    const float* src_token = (const float*)d_in[0];
    const float* src_time  = (const float*)d_in[1];
    const float* norm0_g   = (const float*)d_in[2];
    const float* norm0_b   = (const float*)d_in[3];
    const float* in_w      = (const float*)d_in[4];
    const float* in_b      = (const float*)d_in[5];
    const float* qkv_w     = (const float*)d_in[6];
    const float* qkv_b     = (const float*)d_in[7];
    const float* ao_w      = (const float*)d_in[8];
    const float* ao_b      = (const float*)d_in[9];
    const float* lin1_w    = (const float*)d_in[10];
    const float* lin1_b    = (const float*)d_in[11];
    const float* lin2_w    = (const float*)d_in[12];
    const float* lin2_b    = (const float*)d_in[13];
    const float* n1_g = (const float*)d_in[14];
    const float* n1_b = (const float*)d_in[15];
    const float* n2_g = (const float*)d_in[16];
    const float* n2_b = (const float*)d_in[17];
    const float* n3_g = (const float*)d_in[18];
    const float* n3_b = (const float*)d_in[19];
    const float* n4_g = (const float*)d_in[20];
    const float* n4_b = (const float*)d_in[21];
    const float* out_w = (const float*)d_in[22];
    const float* out_b = (const float*)d_in[23];
    const float* ln_g  = (const float*)d_in[24];
    const float* ln_b  = (const float*)d_in[25];
    float* outp = (float*)d_out;

    static int smem_set = 0;
    if (!smem_set) {
        cudaFuncSetAttribute(attn_tc, cudaFuncAttributeMaxDynamicSharedMemorySize,
                             ATT_SMEM);
        smem_set = 1;
    }

    float *tmp, *xtok, *xtim, *qkv, *attn, *diag, *xc, *ff1, *ff2, *pool, *fin;
    cudaGetSymbolAddress((void**)&tmp,  g_tmp);
    cudaGetSymbolAddress((void**)&xtok, g_xtok);
    cudaGetSymbolAddress((void**)&xtim, g_xtim);
    cudaGetSymbolAddress((void**)&qkv,  g_qkv);
    cudaGetSymbolAddress((void**)&attn, g_attn);
    cudaGetSymbolAddress((void**)&diag, g_diag);
    cudaGetSymbolAddress((void**)&xc,   g_xc);
    cudaGetSymbolAddress((void**)&ff1,  g_ff1);
    cudaGetSymbolAddress((void**)&ff2,  g_ff2);
    cudaGetSymbolAddress((void**)&pool, g_pool);
    cudaGetSymbolAddress((void**)&fin,  g_fin);

    const float* xtok_in = src_token;
    const float* xtim_in = src_time;

    for (int i = 0; i < 2; ++i) {
        const float* n0g = norm0_g + i * 512;
        const float* n0b = norm0_b + i * 512;
        const float* iw  = in_w  + (size_t)i * 512 * 512;
        const float* ib  = in_b  + i * 512;
        const float* qw  = qkv_w + (size_t)i * 1536 * 512;
        const float* qb  = qkv_b + i * 1536;
        const float* aw  = ao_w  + (size_t)i * 512 * 512;
        const float* ab  = ao_b  + i * 512;
        const float* l1w = lin1_w + (size_t)i * 2048 * 768;
        const float* l1b = lin1_b + i * 2048;
        const float* l2w = lin2_w + (size_t)i * 768 * 2048;
        const float* l2b = lin2_b + i * 768;

        ln_warp<<<NROWS / 8, 256>>>(xtok_in, 512, nullptr, 0, nullptr,
                                    n0g, n0b, tmp, 512, 512);
        gemm_tf32<<<dim3(4, 128), 256>>>(tmp, iw, ib, xtok, NROWS, 512, 512, 0);
        gemm_tf32<<<dim3(12, 128), 256>>>(xtok, qw, qb, qkv, NROWS, 1536, 512, 0);
        attn_tc<<<dim3(4, 8, 32), 256, ATT_SMEM>>>(qkv, attn, diag);
        gemm_tf32<<<dim3(4, 128), 256>>>(attn, aw, ab, tmp, NROWS, 512, 512, 0);
        ln_warp<<<NROWS / 8, 256>>>(tmp, 512, xtok, 512, nullptr,
                                    n1_g + i * 512, n1_b + i * 512, xc, 768, 512);
        ln_warp<<<NROWS / 8, 256>>>(xtim_in, 256, nullptr, 0, diag,
                                    n2_g + i * 256, n2_b + i * 256, xc + 512, 768, 256);
        gemm_tf32<<<dim3(16, 128), 256>>>(xc, l1w, l1b, ff1, NROWS, 2048, 768, 1);
        gemm_tf32<<<dim3(6, 128), 256>>>(ff1, l2w, l2b, ff2, NROWS, 768, 2048, 0);
        ln_warp<<<NROWS / 8, 256>>>(ff2, 768, xc, 768, nullptr,
                                    n3_g + i * 512, n3_b + i * 512, xtok, 512, 512);
        ln_warp<<<NROWS / 8, 256>>>(ff2 + 512, 768, xc + 512, 768, nullptr,
                                    n4_g + i * 256, n4_b + i * 256, xtim, 256, 256);

        xtok_in = xtok;
        xtim_in = xtim;
    }

    pool_kernel<<<1024, 256>>>(xtok, xtim, pool);
    gemm_tf32<<<dim3(2, 8), 256>>>(pool, out_w, out_b, fin, 1024, 256, 768, 2);
    ln_warp<<<128, 256>>>(fin, 256, nullptr, 0, nullptr, ln_g, ln_b,
                          outp, 256, 256);
}